// round 8
// baseline (speedup 1.0000x reference)
#include <cuda_runtime.h>
#include <cuda_bf16.h>
#include <cstdint>
#include <cstddef>

// ---------------------------------------------------------------------------
// QUIK quantized linear, M = N = K = 4096.
//   1) global min/max of x and w            (atomic-encoded fp32 reduce)
//   2) quantize x -> packed int8 in [-4,3]
//   3) quantize w -> packed int8, fused per-row fp32 sum (weights_reduced)
//   4) int8 IMMA GEMM (s32 accum == exact) + dequant epilogue
// ---------------------------------------------------------------------------

#define MDIM 4096
#define NDIM 4096
#define KDIM 4096

#define BM 128
#define BN 128
#define BK 64               // int8 elems per k-tile (64 bytes/row)
#define NS 3                // cp.async pipeline stages
#define KT (KDIM / BK)      // 64

#define PITCH 80            // smem row pitch in bytes (64 data + 16 pad, conflict-free)
#define A_STAGE (BM * PITCH)        // 10240 B
#define B_STAGE (BN * PITCH)        // 10240 B
#define SMEM_DYN (NS * (A_STAGE + B_STAGE))   // 61440 B

// Scratch (device globals: allocation-free, harness-legal)
__device__ unsigned g_xmin_u, g_xmax_u, g_wmin_u, g_wmax_u;
__device__ __align__(16) signed char g_xq[(size_t)MDIM * KDIM];
__device__ __align__(16) signed char g_wq[(size_t)NDIM * KDIM];
__device__ float g_wsum[NDIM];

// ---- monotonic float <-> uint encoding for atomicMin/Max ----
__device__ __forceinline__ unsigned fenc(float f) {
    unsigned u = __float_as_uint(f);
    return (u & 0x80000000u) ? ~u : (u | 0x80000000u);
}
__device__ __forceinline__ float fdec(unsigned u) {
    u = (u & 0x80000000u) ? (u & 0x7FFFFFFFu) : ~u;
    return __uint_as_float(u);
}

__global__ void init_kernel() {
    g_xmin_u = 0xFFFFFFFFu; g_xmax_u = 0u;
    g_wmin_u = 0xFFFFFFFFu; g_wmax_u = 0u;
}

// ---------------------------------------------------------------------------
// Min/max reduction (sel: 0 = x globals, 1 = w globals)
// ---------------------------------------------------------------------------
__global__ void minmax_kernel(const float4* __restrict__ p, int n4, int sel) {
    float lmin =  3.402823466e38f;
    float lmax = -3.402823466e38f;
    for (int i = blockIdx.x * blockDim.x + threadIdx.x; i < n4;
         i += gridDim.x * blockDim.x) {
        float4 v = p[i];
        lmin = fminf(lmin, fminf(fminf(v.x, v.y), fminf(v.z, v.w)));
        lmax = fmaxf(lmax, fmaxf(fmaxf(v.x, v.y), fmaxf(v.z, v.w)));
    }
#pragma unroll
    for (int o = 16; o; o >>= 1) {
        lmin = fminf(lmin, __shfl_xor_sync(0xFFFFFFFFu, lmin, o));
        lmax = fmaxf(lmax, __shfl_xor_sync(0xFFFFFFFFu, lmax, o));
    }
    __shared__ float smin[8], smax[8];
    int warp = threadIdx.x >> 5, lane = threadIdx.x & 31;
    if (lane == 0) { smin[warp] = lmin; smax[warp] = lmax; }
    __syncthreads();
    if (threadIdx.x == 0) {
        for (int w = 1; w < 8; w++) {
            lmin = fminf(lmin, smin[w]);
            lmax = fmaxf(lmax, smax[w]);
        }
        if (sel == 0) {
            atomicMin(&g_xmin_u, fenc(lmin));
            atomicMax(&g_xmax_u, fenc(lmax));
        } else {
            atomicMin(&g_wmin_u, fenc(lmin));
            atomicMax(&g_wmax_u, fenc(lmax));
        }
    }
}

// quantize exactly like the reference:
//   clip((t - zero)/scale - 4, -4, 3).astype(int32)  [trunc toward zero]
__device__ __forceinline__ int quant1(float t, float zero, float scale) {
    float v = __fdiv_rn(t - zero, scale) - 4.0f;   // IEEE div even w/ fast-math
    v = fminf(fmaxf(v, -4.0f), 3.0f);
    return (int)v;                                  // trunc toward zero
}

__device__ __forceinline__ unsigned packq4(float4 v, float zero, float scale) {
    int q0 = quant1(v.x, zero, scale);
    int q1 = quant1(v.y, zero, scale);
    int q2 = quant1(v.z, zero, scale);
    int q3 = quant1(v.w, zero, scale);
    return (unsigned)(q0 & 0xFF) | ((unsigned)(q1 & 0xFF) << 8) |
           ((unsigned)(q2 & 0xFF) << 16) | ((unsigned)(q3 & 0xFF) << 24);
}

// ---------------------------------------------------------------------------
// Quantize x -> g_xq (packed int8). 16 values / thread / iter.
// ---------------------------------------------------------------------------
__global__ void quantx_kernel(const float4* __restrict__ x) {
    float zero = fdec(g_xmin_u);
    float scale = (fdec(g_xmax_u) - zero) * 0.125f;
    uint4* dst = reinterpret_cast<uint4*>(g_xq);
    const int n16 = (MDIM * KDIM) / 16;
    for (int i = blockIdx.x * blockDim.x + threadIdx.x; i < n16;
         i += gridDim.x * blockDim.x) {
        uint4 u;
        u.x = packq4(x[i * 4 + 0], zero, scale);
        u.y = packq4(x[i * 4 + 1], zero, scale);
        u.z = packq4(x[i * 4 + 2], zero, scale);
        u.w = packq4(x[i * 4 + 3], zero, scale);
        dst[i] = u;
    }
}

// ---------------------------------------------------------------------------
// Quantize w row -> g_wq (packed int8), fused fp32 row sum. One block per row.
// ---------------------------------------------------------------------------
__global__ void quantw_kernel(const float* __restrict__ w) {
    int row = blockIdx.x;
    int tid = threadIdx.x;
    float zero = fdec(g_wmin_u);
    float scale = (fdec(g_wmax_u) - zero) * 0.125f;
    const float4* src = reinterpret_cast<const float4*>(w + (size_t)row * KDIM);
    uint4* dst = reinterpret_cast<uint4*>(g_wq + (size_t)row * KDIM);
    float sum = 0.0f;
    // 4096 elems = 256 chunks of 16 -> exactly one chunk per thread
    {
        int i = tid;
        float4 v0 = src[i * 4 + 0], v1 = src[i * 4 + 1];
        float4 v2 = src[i * 4 + 2], v3 = src[i * 4 + 3];
        sum = (v0.x + v0.y + v0.z + v0.w) + (v1.x + v1.y + v1.z + v1.w) +
              (v2.x + v2.y + v2.z + v2.w) + (v3.x + v3.y + v3.z + v3.w);
        uint4 u;
        u.x = packq4(v0, zero, scale);
        u.y = packq4(v1, zero, scale);
        u.z = packq4(v2, zero, scale);
        u.w = packq4(v3, zero, scale);
        dst[i] = u;
    }
#pragma unroll
    for (int o = 16; o; o >>= 1) sum += __shfl_xor_sync(0xFFFFFFFFu, sum, o);
    __shared__ float ssum[8];
    int warp = tid >> 5, lane = tid & 31;
    if (lane == 0) ssum[warp] = sum;
    __syncthreads();
    if (tid == 0) {
        float t = ssum[0];
        for (int wq = 1; wq < 8; wq++) t += ssum[wq];
        g_wsum[row] = t;
    }
}

// ---------------------------------------------------------------------------
// GEMM: C = Xq (MxK) * Wq^T (NxK, row-major) int8 -> s32 with dequant epilogue.
// 128x128 block, BK=64, 8 warps (2x4), warp tile 64x32, 3-stage cp.async,
// ldmatrix(b16 view) + mma.sync.m16n8k32.s8.s8.s32.
// ---------------------------------------------------------------------------
__device__ __forceinline__ void cp_async16(uint32_t dst, const void* src) {
    asm volatile("cp.async.cg.shared.global [%0], [%1], 16;\n" :: "r"(dst), "l"(src));
}
__device__ __forceinline__ void cp_commit() {
    asm volatile("cp.async.commit_group;\n");
}
template <int N>
__device__ __forceinline__ void cp_wait() {
    asm volatile("cp.async.wait_group %0;\n" :: "n"(N));
}
__device__ __forceinline__ void ldm_x4(uint32_t addr, uint32_t& r0, uint32_t& r1,
                                       uint32_t& r2, uint32_t& r3) {
    asm volatile("ldmatrix.sync.aligned.m8n8.x4.shared.b16 {%0,%1,%2,%3}, [%4];"
                 : "=r"(r0), "=r"(r1), "=r"(r2), "=r"(r3) : "r"(addr));
}
__device__ __forceinline__ void imma16832(int* c, const uint32_t* a, const uint32_t* b) {
    asm volatile(
        "mma.sync.aligned.m16n8k32.row.col.s32.s8.s8.s32 "
        "{%0,%1,%2,%3}, {%4,%5,%6,%7}, {%8,%9}, {%0,%1,%2,%3};"
        : "+r"(c[0]), "+r"(c[1]), "+r"(c[2]), "+r"(c[3])
        : "r"(a[0]), "r"(a[1]), "r"(a[2]), "r"(a[3]), "r"(b[0]), "r"(b[1]));
}

__global__ __launch_bounds__(256) void gemm_kernel(const float* __restrict__ bias,
                                                   float* __restrict__ out) {
    extern __shared__ char smem[];
    const uint32_t sA = (uint32_t)__cvta_generic_to_shared(smem);
    const uint32_t sB = sA + NS * A_STAGE;

    const int tid = threadIdx.x;
    const int warp = tid >> 5, lane = tid & 31;
    const int wm = warp & 1;   // 0..1 -> m offset wm*64
    const int wn = warp >> 1;  // 0..3 -> n offset wn*32
    const int bm0 = blockIdx.y * BM;
    const int bn0 = blockIdx.x * BN;

    int acc[4][4][4];
#pragma unroll
    for (int mi = 0; mi < 4; mi++)
#pragma unroll
        for (int nf = 0; nf < 4; nf++)
#pragma unroll
            for (int e = 0; e < 4; e++) acc[mi][nf][e] = 0;

    // One k-tile stage: A 128 rows x 64B + B 128 rows x 64B = 1024 x 16B chunks;
    // 256 threads -> 4 chunks each (2 A + 2 B).
    auto load_stage = [&](int s, int ktile) {
#pragma unroll
        for (int i = 0; i < 4; i++) {
            int c = tid + i * 256;                 // 0..1023
            if (c < 512) {
                int row = c >> 2, cc = c & 3;      // cc: 16B unit within 64B row
                cp_async16(sA + (uint32_t)(s * A_STAGE + row * PITCH + cc * 16),
                           g_xq + (size_t)(bm0 + row) * KDIM + ktile * BK + cc * 16);
            } else {
                int c2 = c - 512;
                int row = c2 >> 2, cc = c2 & 3;
                cp_async16(sB + (uint32_t)(s * B_STAGE + row * PITCH + cc * 16),
                           g_wq + (size_t)(bn0 + row) * KDIM + ktile * BK + cc * 16);
            }
        }
    };

    auto compute = [&](int s) {
#pragma unroll
        for (int ks = 0; ks < 2; ks++) {           // 2 x k32 per tile
            const int kb = ks * 32;                // byte offset within 64B row
            uint32_t a[4][4];
#pragma unroll
            for (int mi = 0; mi < 4; mi++) {
                int m = wm * 64 + mi * 16 + (lane & 15);
                uint32_t addr = sA + (uint32_t)(s * A_STAGE + m * PITCH + kb +
                                                ((lane >> 4) << 4));
                ldm_x4(addr, a[mi][0], a[mi][1], a[mi][2], a[mi][3]);
            }
            uint32_t b[4][2];
#pragma unroll
            for (int half = 0; half < 2; half++) {
                int n = wn * 32 + half * 16 + ((lane >> 4) & 1) * 8 + (lane & 7);
                uint32_t addr = sB + (uint32_t)(s * B_STAGE + n * PITCH + kb +
                                                ((lane >> 3) & 1) * 16);
                uint32_t r0, r1, r2, r3;
                ldm_x4(addr, r0, r1, r2, r3);
                b[half * 2][0] = r0;     b[half * 2][1] = r1;
                b[half * 2 + 1][0] = r2; b[half * 2 + 1][1] = r3;
            }
#pragma unroll
            for (int mi = 0; mi < 4; mi++)
#pragma unroll
                for (int nf = 0; nf < 4; nf++)
                    imma16832(acc[mi][nf], a[mi], b[nf]);
        }
    };

    // prologue: stages 0,1 (2 groups in flight)
    load_stage(0, 0); cp_commit();
    load_stage(1, 1); cp_commit();

    for (int kt = 0; kt < KT; kt++) {
        cp_wait<1>();             // tile kt landed (exactly 1 younger group pending)
        __syncthreads();          // also fences prior compute before stage reuse
        if (kt + 2 < KT) load_stage((kt + 2) % NS, kt + 2);
        cp_commit();              // one group per iter keeps the count uniform
        compute(kt % NS);
    }

    // ---- dequant epilogue ----
    const float zx = fdec(g_xmin_u);
    const float sa = (fdec(g_xmax_u) - zx) * 0.125f;
    const float zw = fdec(g_wmin_u);
    const float sw = (fdec(g_wmax_u) - zw) * 0.125f;
    const float s = sa * sw;
    const float coef = zx + 4.0f * sa;
    const int gid = lane >> 2, tig = lane & 3;

#pragma unroll
    for (int mi = 0; mi < 4; mi++) {
        int r0 = bm0 + wm * 64 + mi * 16 + gid;
        float ws0 = coef * g_wsum[r0];
        float ws1 = coef * g_wsum[r0 + 8];
#pragma unroll
        for (int nf = 0; nf < 4; nf++) {
            int c0 = bn0 + wn * 32 + nf * 8 + tig * 2;
            float b0 = __ldg(bias + c0), b1 = __ldg(bias + c0 + 1);
            float2 v0, v1;
            v0.x = (__int2float_rn(acc[mi][nf][0]) + b0) * s + ws0;
            v0.y = (__int2float_rn(acc[mi][nf][1]) + b1) * s + ws0;
            v1.x = (__int2float_rn(acc[mi][nf][2]) + b0) * s + ws1;
            v1.y = (__int2float_rn(acc[mi][nf][3]) + b1) * s + ws1;
            *reinterpret_cast<float2*>(out + (size_t)r0 * NDIM + c0) = v0;
            *reinterpret_cast<float2*>(out + (size_t)(r0 + 8) * NDIM + c0) = v1;
        }
    }
}

// ---------------------------------------------------------------------------
extern "C" void kernel_launch(void* const* d_in, const int* in_sizes, int n_in,
                              void* d_out, int out_size) {
    const float* x    = (const float*)d_in[0];   // [4096, 4096]
    const float* w    = (const float*)d_in[1];   // [4096, 4096]
    const float* bias = (const float*)d_in[2];   // [4096]
    float* out = (float*)d_out;                  // [4096, 4096]
    (void)in_sizes; (void)n_in; (void)out_size;

    init_kernel<<<1, 1>>>();
    const int n4 = (MDIM * KDIM) / 4;
    minmax_kernel<<<1024, 256>>>((const float4*)x, n4, 0);
    minmax_kernel<<<1024, 256>>>((const float4*)w, n4, 1);
    quantx_kernel<<<4096, 256>>>((const float4*)x);
    quantw_kernel<<<NDIM, 256>>>(w);

    cudaFuncSetAttribute(gemm_kernel,
                         cudaFuncAttributeMaxDynamicSharedMemorySize, SMEM_DYN);
    dim3 grid(NDIM / BN, MDIM / BM);   // (32, 32)
    gemm_kernel<<<grid, 256, SMEM_DYN>>>(bias, out);
}

// round 13
// speedup vs baseline: 2.3158x; 2.3158x over previous
#include <cuda_runtime.h>
#include <cuda_bf16.h>
#include <cstdint>
#include <cstddef>

// ---------------------------------------------------------------------------
// QUIK quantized linear, M = N = K = 4096.
//   1) global min/max of x and w            (atomic-encoded fp32 reduce)
//   2) quantize x -> bf16 ints in [-4,3]
//   3) quantize w -> bf16 ints, fused per-row fp32 sum (weights_reduced)
//   4) bf16 HMMA GEMM (fp32 accum == exact integer GEMM) + dequant epilogue
//      occupancy 2, BK=64 double-buffered cp.async pipeline
// ---------------------------------------------------------------------------

#define MDIM 4096
#define NDIM 4096
#define KDIM 4096

#define BM 128
#define BN 128
#define BK 64               // bf16 elems per k-tile (128 bytes/row)
#define KT (KDIM / BK)      // 64

#define PITCHB 144          // smem row pitch bytes (128 data + 16 pad -> conflict-free)
#define A_STAGE (BM * PITCHB)              // 18432 B
#define B_STAGE (BN * PITCHB)              // 18432 B
#define SMEM_DYN (2 * (A_STAGE + B_STAGE)) // 73728 B (2 stages)

// Scratch (device globals: allocation-free, harness-legal)
__device__ unsigned g_xmin_u, g_xmax_u, g_wmin_u, g_wmax_u;
__device__ __align__(16) __nv_bfloat16 g_xq[(size_t)MDIM * KDIM];
__device__ __align__(16) __nv_bfloat16 g_wq[(size_t)NDIM * KDIM];
__device__ float g_wsum[NDIM];

// ---- monotonic float <-> uint encoding for atomicMin/Max ----
__device__ __forceinline__ unsigned fenc(float f) {
    unsigned u = __float_as_uint(f);
    return (u & 0x80000000u) ? ~u : (u | 0x80000000u);
}
__device__ __forceinline__ float fdec(unsigned u) {
    u = (u & 0x80000000u) ? (u & 0x7FFFFFFFu) : ~u;
    return __uint_as_float(u);
}

__global__ void init_kernel() {
    g_xmin_u = 0xFFFFFFFFu; g_xmax_u = 0u;
    g_wmin_u = 0xFFFFFFFFu; g_wmax_u = 0u;
}

// ---------------------------------------------------------------------------
// Min/max reduction (sel: 0 = x globals, 1 = w globals)
// ---------------------------------------------------------------------------
__global__ void minmax_kernel(const float4* __restrict__ p, int n4, int sel) {
    float lmin =  3.402823466e38f;
    float lmax = -3.402823466e38f;
    for (int i = blockIdx.x * blockDim.x + threadIdx.x; i < n4;
         i += gridDim.x * blockDim.x) {
        float4 v = p[i];
        lmin = fminf(lmin, fminf(fminf(v.x, v.y), fminf(v.z, v.w)));
        lmax = fmaxf(lmax, fmaxf(fmaxf(v.x, v.y), fmaxf(v.z, v.w)));
    }
#pragma unroll
    for (int o = 16; o; o >>= 1) {
        lmin = fminf(lmin, __shfl_xor_sync(0xFFFFFFFFu, lmin, o));
        lmax = fmaxf(lmax, __shfl_xor_sync(0xFFFFFFFFu, lmax, o));
    }
    __shared__ float smin[8], smax[8];
    int warp = threadIdx.x >> 5, lane = threadIdx.x & 31;
    if (lane == 0) { smin[warp] = lmin; smax[warp] = lmax; }
    __syncthreads();
    if (threadIdx.x == 0) {
        for (int w = 1; w < 8; w++) {
            lmin = fminf(lmin, smin[w]);
            lmax = fmaxf(lmax, smax[w]);
        }
        if (sel == 0) {
            atomicMin(&g_xmin_u, fenc(lmin));
            atomicMax(&g_xmax_u, fenc(lmax));
        } else {
            atomicMin(&g_wmin_u, fenc(lmin));
            atomicMax(&g_wmax_u, fenc(lmax));
        }
    }
}

// quantize exactly like the reference:
//   clip((t - zero)/scale - 4, -4, 3).astype(int32)  [trunc toward zero]
__device__ __forceinline__ int quant1(float t, float zero, float scale) {
    float v = __fdiv_rn(t - zero, scale) - 4.0f;   // IEEE div even w/ fast-math
    v = fminf(fmaxf(v, -4.0f), 3.0f);
    return (int)v;                                  // trunc toward zero
}

__device__ __forceinline__ unsigned packq2(float a, float b, float zero, float scale) {
    __nv_bfloat162 h = __floats2bfloat162_rn((float)quant1(a, zero, scale),
                                             (float)quant1(b, zero, scale));
    return *reinterpret_cast<unsigned*>(&h);
}

__global__ void quantx_kernel(const float4* __restrict__ x) {
    float zero = fdec(g_xmin_u);
    float scale = (fdec(g_xmax_u) - zero) * 0.125f;
    uint2* dst = reinterpret_cast<uint2*>(g_xq);
    const int n4 = (MDIM * KDIM) / 4;
    for (int i = blockIdx.x * blockDim.x + threadIdx.x; i < n4;
         i += gridDim.x * blockDim.x) {
        float4 v = x[i];
        uint2 u;
        u.x = packq2(v.x, v.y, zero, scale);
        u.y = packq2(v.z, v.w, zero, scale);
        dst[i] = u;
    }
}

__global__ void quantw_kernel(const float* __restrict__ w) {
    int row = blockIdx.x;
    int tid = threadIdx.x;
    float zero = fdec(g_wmin_u);
    float scale = (fdec(g_wmax_u) - zero) * 0.125f;
    const float4* src = reinterpret_cast<const float4*>(w + (size_t)row * KDIM);
    uint2* dst = reinterpret_cast<uint2*>(g_wq + (size_t)row * KDIM);
    float sum = 0.0f;
    for (int i = tid; i < KDIM / 4; i += 256) {
        float4 v = src[i];
        sum += (v.x + v.y) + (v.z + v.w);
        uint2 u;
        u.x = packq2(v.x, v.y, zero, scale);
        u.y = packq2(v.z, v.w, zero, scale);
        dst[i] = u;
    }
#pragma unroll
    for (int o = 16; o; o >>= 1) sum += __shfl_xor_sync(0xFFFFFFFFu, sum, o);
    __shared__ float ssum[8];
    int warp = tid >> 5, lane = tid & 31;
    if (lane == 0) ssum[warp] = sum;
    __syncthreads();
    if (tid == 0) {
        float t = ssum[0];
        for (int wq = 1; wq < 8; wq++) t += ssum[wq];
        g_wsum[row] = t;
    }
}

// ---------------------------------------------------------------------------
// GEMM: C = Xq (MxK) * Wq^T (NxK row-major) with dequant epilogue.
// 128x128 block tile, BK=64, 8 warps (2x4), warp tile 64x32,
// cp.async double-buffered smem, ldmatrix + mma.sync.m16n8k16 bf16/f32.
// Occupancy 2 CTAs/SM.
// ---------------------------------------------------------------------------
__device__ __forceinline__ void cp_async16(uint32_t dst, const void* src) {
    asm volatile("cp.async.cg.shared.global [%0], [%1], 16;\n" :: "r"(dst), "l"(src));
}
__device__ __forceinline__ void cp_commit() {
    asm volatile("cp.async.commit_group;\n");
}
__device__ __forceinline__ void cp_wait0() {
    asm volatile("cp.async.wait_group 0;\n");
}
__device__ __forceinline__ void ldm_x4(uint32_t addr, uint32_t& r0, uint32_t& r1,
                                       uint32_t& r2, uint32_t& r3) {
    asm volatile("ldmatrix.sync.aligned.m8n8.x4.shared.b16 {%0,%1,%2,%3}, [%4];"
                 : "=r"(r0), "=r"(r1), "=r"(r2), "=r"(r3) : "r"(addr));
}
__device__ __forceinline__ void mma16816(float* c, const uint32_t* a, const uint32_t* b) {
    asm volatile(
        "mma.sync.aligned.m16n8k16.row.col.f32.bf16.bf16.f32 "
        "{%0,%1,%2,%3}, {%4,%5,%6,%7}, {%8,%9}, {%0,%1,%2,%3};"
        : "+f"(c[0]), "+f"(c[1]), "+f"(c[2]), "+f"(c[3])
        : "r"(a[0]), "r"(a[1]), "r"(a[2]), "r"(a[3]), "r"(b[0]), "r"(b[1]));
}

__global__ __launch_bounds__(256, 2) void gemm_kernel(const float* __restrict__ bias,
                                                      float* __restrict__ out) {
    extern __shared__ char smem[];
    const uint32_t sA = (uint32_t)__cvta_generic_to_shared(smem);
    const uint32_t sB = sA + 2 * A_STAGE;

    const int tid = threadIdx.x;
    const int warp = tid >> 5, lane = tid & 31;
    const int wm = warp & 1;   // 0..1 -> m offset wm*64
    const int wn = warp >> 1;  // 0..3 -> n offset wn*32
    const int bm0 = blockIdx.y * BM;
    const int bn0 = blockIdx.x * BN;

    float acc[4][4][4];
#pragma unroll
    for (int mi = 0; mi < 4; mi++)
#pragma unroll
        for (int nf = 0; nf < 4; nf++)
#pragma unroll
            for (int e = 0; e < 4; e++) acc[mi][nf][e] = 0.0f;

    // One stage: A 128 rows x 128B + B 128 rows x 128B = 2048 x 16B chunks;
    // 256 threads -> 8 chunks each (4 A + 4 B).
    auto load_stage = [&](int s, int ktile) {
#pragma unroll
        for (int i = 0; i < 8; i++) {
            int c = tid + i * 256;                 // 0..2047
            if (c < 1024) {
                int row = c >> 3, cc = c & 7;      // cc: 16B unit within 128B row
                cp_async16(sA + (uint32_t)(s * A_STAGE + row * PITCHB + cc * 16),
                           g_xq + (size_t)(bm0 + row) * KDIM + ktile * BK + cc * 8);
            } else {
                int c2 = c - 1024;
                int row = c2 >> 3, cc = c2 & 7;
                cp_async16(sB + (uint32_t)(s * B_STAGE + row * PITCHB + cc * 16),
                           g_wq + (size_t)(bn0 + row) * KDIM + ktile * BK + cc * 8);
            }
        }
    };

    auto compute = [&](int s) {
#pragma unroll
        for (int ks = 0; ks < 4; ks++) {           // 4 x k16 per BK=64 tile
            const int kb = ks * 32;                // byte offset within 128B row
            uint32_t a[4][4];
#pragma unroll
            for (int mi = 0; mi < 4; mi++) {
                int m = wm * 64 + mi * 16 + (lane & 15);
                uint32_t addr = sA + (uint32_t)(s * A_STAGE + m * PITCHB + kb +
                                                ((lane >> 4) << 4));
                ldm_x4(addr, a[mi][0], a[mi][1], a[mi][2], a[mi][3]);
            }
            uint32_t b[4][2];
#pragma unroll
            for (int half = 0; half < 2; half++) {
                int n = wn * 32 + half * 16 + ((lane >> 4) & 1) * 8 + (lane & 7);
                uint32_t addr = sB + (uint32_t)(s * B_STAGE + n * PITCHB + kb +
                                                ((lane >> 3) & 1) * 16);
                uint32_t r0, r1, r2, r3;
                ldm_x4(addr, r0, r1, r2, r3);
                b[half * 2][0] = r0;     b[half * 2][1] = r1;
                b[half * 2 + 1][0] = r2; b[half * 2 + 1][1] = r3;
            }
#pragma unroll
            for (int mi = 0; mi < 4; mi++)
#pragma unroll
                for (int nf = 0; nf < 4; nf++)
                    mma16816(acc[mi][nf], a[mi], b[nf]);
        }
    };

    load_stage(0, 0);
    cp_commit();
    cp_wait0();
    __syncthreads();
    for (int kt = 0; kt < KT; kt++) {
        int cur = kt & 1;
        if (kt + 1 < KT) {
            load_stage(cur ^ 1, kt + 1);   // overlaps with compute below
            cp_commit();
        }
        compute(cur);
        if (kt + 1 < KT) cp_wait0();
        __syncthreads();
    }

    // ---- dequant epilogue ----
    const float zx = fdec(g_xmin_u);
    const float sa = (fdec(g_xmax_u) - zx) * 0.125f;
    const float zw = fdec(g_wmin_u);
    const float sw = (fdec(g_wmax_u) - zw) * 0.125f;
    const float s = sa * sw;
    const float coef = zx + 4.0f * sa;
    const int gid = lane >> 2, tig = lane & 3;

#pragma unroll
    for (int mi = 0; mi < 4; mi++) {
        int r0 = bm0 + wm * 64 + mi * 16 + gid;
        float ws0 = coef * g_wsum[r0];
        float ws1 = coef * g_wsum[r0 + 8];
#pragma unroll
        for (int nf = 0; nf < 4; nf++) {
            int c0 = bn0 + wn * 32 + nf * 8 + tig * 2;
            float b0 = __ldg(bias + c0), b1 = __ldg(bias + c0 + 1);
            float2 v0, v1;
            v0.x = (acc[mi][nf][0] + b0) * s + ws0;
            v0.y = (acc[mi][nf][1] + b1) * s + ws0;
            v1.x = (acc[mi][nf][2] + b0) * s + ws1;
            v1.y = (acc[mi][nf][3] + b1) * s + ws1;
            *reinterpret_cast<float2*>(out + (size_t)r0 * NDIM + c0) = v0;
            *reinterpret_cast<float2*>(out + (size_t)(r0 + 8) * NDIM + c0) = v1;
        }
    }
}

// ---------------------------------------------------------------------------
extern "C" void kernel_launch(void* const* d_in, const int* in_sizes, int n_in,
                              void* d_out, int out_size) {
    const float* x    = (const float*)d_in[0];   // [4096, 4096]
    const float* w    = (const float*)d_in[1];   // [4096, 4096]
    const float* bias = (const float*)d_in[2];   // [4096]
    float* out = (float*)d_out;                  // [4096, 4096]
    (void)in_sizes; (void)n_in; (void)out_size;

    init_kernel<<<1, 1>>>();
    const int n4 = (MDIM * KDIM) / 4;
    minmax_kernel<<<1024, 256>>>((const float4*)x, n4, 0);
    minmax_kernel<<<1024, 256>>>((const float4*)w, n4, 1);
    quantx_kernel<<<8192, 256>>>((const float4*)x);
    quantw_kernel<<<NDIM, 256>>>(w);

    cudaFuncSetAttribute(gemm_kernel,
                         cudaFuncAttributeMaxDynamicSharedMemorySize, SMEM_DYN);
    dim3 grid(NDIM / BN, MDIM / BM);   // (32, 32)
    gemm_kernel<<<grid, 256, SMEM_DYN>>>(bias, out);
}